// round 1
// baseline (speedup 1.0000x reference)
#include <cuda_runtime.h>
#include <math.h>

#define B_  16
#define L_  4096
#define H_  512
#define NT_ 8
#define IN_ 10
#define OUT_ 1032
#define HH_ 256
#define NC_ 16
#define CH_ 256
#define EPS_ 1e-5f
#define NROW (B_*L_)

// ---------------- device scratch (static, allocation-free) ----------------
__device__ float g_xc[NROW*IN_];                    // [row][10] : x0,x1,te[8]
__device__ float g_F [(size_t)NROW*OUT_];           // fused features [row][1032]
__device__ float g_W [4][H_][IN_];                  // folded gate weights: fz,fh,bz,bh
__device__ float g_bias[4][H_];
__device__ float g_P [2][B_][NC_][H_];              // chunk a-products
__device__ float g_Ae[2][B_][NC_][H_];              // chunk-entry cumprod state
__device__ float g_Lc[2][B_][NC_][H_];              // chunk local sums of d
__device__ float g_Se[2][B_][NC_][H_];              // chunk-entry cumsum state
__device__ float g_G [OUT_*HH_];                    // folded LN*gh_w1, [j][k]
__device__ float g_sv[HH_];                         // column sums of G
__device__ float g_cv[HH_];                         // folded bias

// ---------------- prep: fold gate weights through the 10-dim projection ----
__global__ void k_fold(const float* __restrict__ fz, const float* __restrict__ fh,
                       const float* __restrict__ bz, const float* __restrict__ bh,
                       const float* __restrict__ fzb, const float* __restrict__ fhb,
                       const float* __restrict__ bzb, const float* __restrict__ bhb,
                       const float* __restrict__ fp, const float* __restrict__ fpb,
                       const float* __restrict__ bp, const float* __restrict__ bpb) {
    int p = blockIdx.x;            // 0:fz 1:fh 2:bz 3:bh
    int h = threadIdx.x;           // 512
    const float* zw = (p==0)?fz:(p==1)?fh:(p==2)?bz:bh;
    const float* zb = (p==0)?fzb:(p==1)?fhb:(p==2)?bzb:bhb;
    const float* pw = (p<2)?fp:bp;
    const float* pb = (p<2)?fpb:bpb;
    float acc[IN_]; float ab = 0.f;
    #pragma unroll
    for (int i=0;i<IN_;i++) acc[i]=0.f;
    for (int d=0; d<H_; d++) {
        float w = zw[h*H_+d];
        #pragma unroll
        for (int i=0;i<IN_;i++) acc[i] += w*pw[d*IN_+i];
        ab += w*pb[d];
    }
    #pragma unroll
    for (int i=0;i<IN_;i++) g_W[p][h][i]=acc[i];
    g_bias[p][h] = ab + zb[h];
}

// ---------------- prep: fold LN affine (+time_scale) into gh_w1 ------------
__global__ void k_prepG(const float* __restrict__ gw1, const float* __restrict__ gb1,
                        const float* __restrict__ lng, const float* __restrict__ lnb,
                        const float* __restrict__ tscp) {
    int k = threadIdx.x;  // 256
    float tsc = tscp[0];
    float s = 0.f, c = 0.f;
    for (int j=0;j<OUT_;j++) {
        float sc = (j >= OUT_-NT_) ? tsc : 1.0f;
        float w  = gw1[k*OUT_+j];
        float Gv = lng[j]*sc*w;
        g_G[j*HH_+k] = Gv;
        s += Gv;
        c += lnb[j]*sc*w;
    }
    g_sv[k] = s;
    g_cv[k] = c + gb1[k];
}

// ---------------- prep: time embedding + xc, write te into F ---------------
__global__ void k_te(const float* __restrict__ x, const float* __restrict__ t,
                     const float* __restrict__ w1, const float* __restrict__ b1,
                     const float* __restrict__ w2, const float* __restrict__ b2) {
    int row = blockIdx.x*blockDim.x + threadIdx.x;
    if (row >= NROW) return;
    int b = row / L_;
    float ts = t[row] - t[b*L_];
    float r[NT_];
    #pragma unroll
    for (int j=0;j<NT_;j++) r[j] = fmaxf(ts*w1[j] + b1[j], 0.0f);
    #pragma unroll
    for (int k=0;k<NT_;k++) {
        float a = b2[k];
        #pragma unroll
        for (int j=0;j<NT_;j++) a += r[j]*w2[k*NT_+j];
        g_xc[row*IN_+2+k] = a;
        g_F[(size_t)row*OUT_ + (OUT_-NT_) + k] = a;
    }
    g_xc[row*IN_+0] = x[row*2+0];
    g_xc[row*IN_+1] = x[row*2+1];
}

// ---------------- scan pass A: chunk-local a-products ----------------------
__global__ void k_scanA() {
    int c = blockIdx.x, b = blockIdx.y, dir = blockIdx.z;
    int h = threadIdx.x;
    __shared__ float xs[CH_][IN_];
    const float* xcb = g_xc + ((size_t)b*L_ + (size_t)c*CH_)*IN_;
    for (int i=h; i<CH_*IN_; i+=H_) ((float*)xs)[i] = xcb[i];
    float wz[IN_]; float bz;
    int pz = dir*2;
    #pragma unroll
    for (int i=0;i<IN_;i++) wz[i] = g_W[pz][h][i];
    bz = g_bias[pz][h];
    __syncthreads();
    float A = 1.0f;
    if (dir==0) {
        for (int s=0;s<CH_;s++) {
            float arg = bz;
            #pragma unroll
            for (int i=0;i<IN_;i++) arg += xs[s][i]*wz[i];
            float z = 1.0f/(1.0f+expf(-arg));
            A = A*(1.0f - z);
        }
    } else {
        for (int s=CH_-1;s>=0;s--) {
            float arg = bz;
            #pragma unroll
            for (int i=0;i<IN_;i++) arg += xs[s][i]*wz[i];
            float z = 1.0f/(1.0f+expf(-arg));
            A = A*(1.0f - z);
        }
    }
    g_P[dir][b][c][h] = A;
}

// ---------------- scan pass B1: chunk-entry cumprod states -----------------
__global__ void k_scanB1() {
    int b = blockIdx.x, dir = blockIdx.y, h = threadIdx.x;
    float run = 1.0f;
    if (dir==0) { for (int c=0;c<NC_;c++)      { g_Ae[0][b][c][h]=run; run *= g_P[0][b][c][h]; } }
    else        { for (int c=NC_-1;c>=0;c--)   { g_Ae[1][b][c][h]=run; run *= g_P[1][b][c][h]; } }
}

// ---------------- scan pass C1: chunk local sums of d = b/clip(A) ----------
__global__ void k_scanC1() {
    int c = blockIdx.x, b = blockIdx.y, dir = blockIdx.z;
    int h = threadIdx.x;
    __shared__ float xs[CH_][IN_];
    const float* xcb = g_xc + ((size_t)b*L_ + (size_t)c*CH_)*IN_;
    for (int i=h; i<CH_*IN_; i+=H_) ((float*)xs)[i] = xcb[i];
    float wz[IN_], wh[IN_]; float bz, bh;
    int pz = dir*2, ph = dir*2+1;
    #pragma unroll
    for (int i=0;i<IN_;i++) { wz[i]=g_W[pz][h][i]; wh[i]=g_W[ph][h][i]; }
    bz = g_bias[pz][h]; bh = g_bias[ph][h];
    __syncthreads();
    float A = g_Ae[dir][b][c][h];
    float Ls = 0.0f;
    int s0  = (dir==0)? 0 : CH_-1;
    int ds  = (dir==0)? 1 : -1;
    for (int k=0;k<CH_;k++) {
        int s = s0 + k*ds;
        float az = bz, ah = bh;
        #pragma unroll
        for (int i=0;i<IN_;i++) { float xv = xs[s][i]; az += xv*wz[i]; ah += xv*wh[i]; }
        float z = 1.0f/(1.0f+expf(-az));
        A = A*(1.0f - z);
        float bb = z*ah;
        Ls += __fdividef(bb, fmaxf(A, 1e-12f));
    }
    g_Lc[dir][b][c][h] = Ls;
}

// ---------------- scan pass B2: chunk-entry cumsum states ------------------
__global__ void k_scanB2() {
    int b = blockIdx.x, dir = blockIdx.y, h = threadIdx.x;
    float run = 0.0f;
    if (dir==0) { for (int c=0;c<NC_;c++)    { g_Se[0][b][c][h]=run; run += g_Lc[0][b][c][h]; } }
    else        { for (int c=NC_-1;c>=0;c--) { g_Se[1][b][c][h]=run; run += g_Lc[1][b][c][h]; } }
}

// ---------------- scan pass C2: emit shifted h = A*S into F ----------------
__global__ void k_scanC2() {
    int c = blockIdx.x, b = blockIdx.y, dir = blockIdx.z;
    int h = threadIdx.x;
    __shared__ float xs[CH_][IN_];
    const float* xcb = g_xc + ((size_t)b*L_ + (size_t)c*CH_)*IN_;
    for (int i=h; i<CH_*IN_; i+=H_) ((float*)xs)[i] = xcb[i];
    float wz[IN_], wh[IN_]; float bz, bh;
    int pz = dir*2, ph = dir*2+1;
    #pragma unroll
    for (int i=0;i<IN_;i++) { wz[i]=g_W[pz][h][i]; wh[i]=g_W[ph][h][i]; }
    bz = g_bias[pz][h]; bh = g_bias[ph][h];
    __syncthreads();
    float A = g_Ae[dir][b][c][h];
    float S = g_Se[dir][b][c][h];
    int s0  = (dir==0)? 0 : CH_-1;
    int ds  = (dir==0)? 1 : -1;
    size_t fofs = (dir==0)? (size_t)h : (size_t)(H_ + h);
    for (int k=0;k<CH_;k++) {
        int s = s0 + k*ds;
        int l = c*CH_ + s;
        // shifted output: state BEFORE consuming position l
        g_F[((size_t)(b*L_ + l))*OUT_ + fofs] = A*S;
        float az = bz, ah = bh;
        #pragma unroll
        for (int i=0;i<IN_;i++) { float xv = xs[s][i]; az += xv*wz[i]; ah += xv*wh[i]; }
        float z = 1.0f/(1.0f+expf(-az));
        A = A*(1.0f - z);
        float bb = z*ah;
        S += __fdividef(bb, fmaxf(A, 1e-12f));
    }
}

// ---------------- fused GEMM (65536x1032 @ 1032x256) + LN-correction + gelu + w2 reduce
#define BM 64
#define BK 8
__global__ __launch_bounds__(256) void k_gemm(const float* __restrict__ w2,
                                              const float* __restrict__ b2p,
                                              float* __restrict__ out) {
    __shared__ float As[BM][BK];
    __shared__ float Bs[BK][HH_];
    __shared__ float s_s[HH_], s_c[HH_], s_w2[HH_];
    __shared__ float s_sum[BM], s_sq[BM];
    __shared__ float s_mu[BM], s_rsig[BM];
    __shared__ float s_part[BM][16];

    int t  = threadIdx.x;
    int tx = t & 15, ty = t >> 4;
    int row0 = blockIdx.x*BM;

    s_s[t] = g_sv[t]; s_c[t] = g_cv[t]; s_w2[t] = w2[t];
    if (t < BM) { s_sum[t] = 0.f; s_sq[t] = 0.f; }

    float acc[4][16];
    #pragma unroll
    for (int i=0;i<4;i++)
        #pragma unroll
        for (int j=0;j<16;j++) acc[i][j]=0.f;

    int ar = t >> 2;          // A-load row (fixed per thread)
    int ak = (t & 3)*2;       // A-load k pair
    int bn = (t & 63)*4, bk = t >> 6;
    const float* Arow = g_F + ((size_t)(row0+ar))*OUT_ + ak;
    float psum = 0.f, psq = 0.f;

    for (int kc=0; kc<OUT_/BK; kc++) {
        float2 av  = *(const float2*)(Arow + kc*BK);
        float4 bv0 = *(const float4*)(g_G + (size_t)(kc*BK+bk  )*HH_ + bn);
        float4 bv1 = *(const float4*)(g_G + (size_t)(kc*BK+bk+4)*HH_ + bn);
        psum += av.x + av.y;
        psq  += av.x*av.x + av.y*av.y;
        __syncthreads();
        *(float2*)&As[ar][ak]  = av;
        *(float4*)&Bs[bk][bn]   = bv0;
        *(float4*)&Bs[bk+4][bn] = bv1;
        __syncthreads();
        #pragma unroll
        for (int kk=0; kk<BK; kk+=2) {
            float2 a2[4];
            #pragma unroll
            for (int i=0;i<4;i++) a2[i] = *(float2*)&As[ty*4+i][kk];
            float4 bva[4], bvb[4];
            #pragma unroll
            for (int g=0; g<4; g++) {
                bva[g] = *(float4*)&Bs[kk  ][tx*4 + g*64];
                bvb[g] = *(float4*)&Bs[kk+1][tx*4 + g*64];
            }
            #pragma unroll
            for (int i=0;i<4;i++) {
                #pragma unroll
                for (int g=0; g<4; g++) {
                    acc[i][g*4+0] += a2[i].x*bva[g].x + a2[i].y*bvb[g].x;
                    acc[i][g*4+1] += a2[i].x*bva[g].y + a2[i].y*bvb[g].y;
                    acc[i][g*4+2] += a2[i].x*bva[g].z + a2[i].y*bvb[g].z;
                    acc[i][g*4+3] += a2[i].x*bva[g].w + a2[i].y*bvb[g].w;
                }
            }
        }
    }

    atomicAdd(&s_sum[ar], psum);
    atomicAdd(&s_sq[ar],  psq);
    __syncthreads();
    if (t < BM) {
        float m = s_sum[t] * (1.0f/(float)OUT_);
        float v = s_sq[t]  * (1.0f/(float)OUT_) - m*m;
        s_mu[t]   = m;
        s_rsig[t] = 1.0f/sqrtf(v + EPS_);
    }
    __syncthreads();

    float po[4] = {0.f,0.f,0.f,0.f};
    #pragma unroll
    for (int i=0;i<4;i++) {
        int r = ty*4+i;
        float mu = s_mu[r], rs = s_rsig[r];
        #pragma unroll
        for (int g=0; g<4; g++) {
            #pragma unroll
            for (int e=0; e<4; e++) {
                int col = tx*4 + g*64 + e;
                float a1 = (acc[i][g*4+e] - mu*s_s[col])*rs + s_c[col];
                float h1 = 0.5f*a1*(1.0f + erff(a1*0.70710678118654752440f));
                po[i] += h1 * s_w2[col];
            }
        }
    }
    #pragma unroll
    for (int i=0;i<4;i++) s_part[ty*4+i][tx] = po[i];
    __syncthreads();
    if (t < BM) {
        float o = b2p[0];
        #pragma unroll
        for (int j=0;j<16;j++) o += s_part[t][j];
        out[row0 + t] = o;
    }
}

// ---------------- launch ---------------------------------------------------
extern "C" void kernel_launch(void* const* d_in, const int* in_sizes, int n_in,
                              void* d_out, int out_size) {
    const float* x      = (const float*)d_in[0];
    const float* t      = (const float*)d_in[1];
    const float* te_w1  = (const float*)d_in[2];
    const float* te_b1  = (const float*)d_in[3];
    const float* te_w2  = (const float*)d_in[4];
    const float* te_b2  = (const float*)d_in[5];
    const float* fproj_w= (const float*)d_in[6];
    const float* fproj_b= (const float*)d_in[7];
    const float* bproj_w= (const float*)d_in[8];
    const float* bproj_b= (const float*)d_in[9];
    const float* fz_w   = (const float*)d_in[10];
    const float* fz_b   = (const float*)d_in[11];
    const float* fh_w   = (const float*)d_in[12];
    const float* fh_b   = (const float*)d_in[13];
    const float* bz_w   = (const float*)d_in[14];
    const float* bz_b   = (const float*)d_in[15];
    const float* bh_w   = (const float*)d_in[16];
    const float* bh_b   = (const float*)d_in[17];
    const float* ln_g   = (const float*)d_in[18];
    const float* ln_b   = (const float*)d_in[19];
    const float* tsc    = (const float*)d_in[20];
    const float* gh_w1  = (const float*)d_in[21];
    const float* gh_b1  = (const float*)d_in[22];
    const float* gh_w2  = (const float*)d_in[23];
    const float* gh_b2  = (const float*)d_in[24];
    float* out = (float*)d_out;

    k_fold<<<4, H_>>>(fz_w, fh_w, bz_w, bh_w, fz_b, fh_b, bz_b, bh_b,
                      fproj_w, fproj_b, bproj_w, bproj_b);
    k_prepG<<<1, HH_>>>(gh_w1, gh_b1, ln_g, ln_b, tsc);
    k_te<<<NROW/256, 256>>>(x, t, te_w1, te_b1, te_w2, te_b2);
    k_scanA <<<dim3(NC_, B_, 2), H_>>>();
    k_scanB1<<<dim3(B_, 2), H_>>>();
    k_scanC1<<<dim3(NC_, B_, 2), H_>>>();
    k_scanB2<<<dim3(B_, 2), H_>>>();
    k_scanC2<<<dim3(NC_, B_, 2), H_>>>();
    k_gemm<<<NROW/BM, 256>>>(gh_w2, gh_b2, out);
}

// round 2
// speedup vs baseline: 1.8314x; 1.8314x over previous
#include <cuda_runtime.h>
#include <math.h>
#include <stdint.h>

#define B_  16
#define L_  4096
#define H_  512
#define NT_ 8
#define IN_ 10
#define OUT_ 1032
#define HH_ 256
#define NC_ 16
#define CH_ 256
#define EPS_ 1e-5f
#define NROW (B_*L_)
#define NKT (OUT_/8)      // 129 k-tiles of 8

// ---------------- device scratch (static, allocation-free) ----------------
__device__ float g_xc[NROW*IN_];                    // [row][10]
__device__ float g_F [(size_t)NROW*OUT_];           // fused features [row][1032]
__device__ float g_W [4][H_][IN_];                  // folded gate weights
__device__ float g_bias[4][H_];
__device__ float g_P [2][B_][NC_][H_];
__device__ float g_Ae[2][B_][NC_][H_];
__device__ float g_Lc[2][B_][NC_][H_];
__device__ float g_Se[2][B_][NC_][H_];
__device__ float g_Gf[NKT*32*64];                   // B in mma-fragment-major layout
__device__ float g_sv[HH_];
__device__ float g_cv[HH_];

__device__ __forceinline__ uint32_t f2tf32(float f) {
    uint32_t r;
    asm("cvt.rna.tf32.f32 %0, %1;" : "=r"(r) : "f"(f));
    return r;
}

// ---------------- zero accumulators ----------------------------------------
__global__ void k_zero() {
    int i = blockIdx.x*blockDim.x + threadIdx.x;
    if (i < 4*H_*IN_) ((float*)g_W)[i] = 0.f;
    if (i < 4*H_)     ((float*)g_bias)[i] = 0.f;
    if (i < HH_)      { g_sv[i] = 0.f; g_cv[i] = 0.f; }
}

// ---------------- fold gate weights through the 10-dim projection ----------
__global__ void k_fold(const float* __restrict__ fz, const float* __restrict__ fh,
                       const float* __restrict__ bz, const float* __restrict__ bh,
                       const float* __restrict__ fzb, const float* __restrict__ fhb,
                       const float* __restrict__ bzb, const float* __restrict__ bhb,
                       const float* __restrict__ fp, const float* __restrict__ fpb,
                       const float* __restrict__ bp, const float* __restrict__ bpb) {
    int p = blockIdx.x;            // 0:fz 1:fh 2:bz 3:bh
    int sl = blockIdx.y;           // d-slice 0..7 (64 each)
    int h = threadIdx.x;
    const float* zw = (p==0)?fz:(p==1)?fh:(p==2)?bz:bh;
    const float* zb = (p==0)?fzb:(p==1)?fhb:(p==2)?bzb:bhb;
    const float* pw = (p<2)?fp:bp;
    const float* pb = (p<2)?fpb:bpb;
    float acc[IN_]; float ab = 0.f;
    #pragma unroll
    for (int i=0;i<IN_;i++) acc[i]=0.f;
    for (int d=sl*64; d<sl*64+64; d++) {
        float w = zw[h*H_+d];
        #pragma unroll
        for (int i=0;i<IN_;i++) acc[i] += w*pw[d*IN_+i];
        ab += w*pb[d];
    }
    #pragma unroll
    for (int i=0;i<IN_;i++) atomicAdd(&g_W[p][h][i], acc[i]);
    atomicAdd(&g_bias[p][h], ab + ((sl==0)? zb[h] : 0.f));
}

// ---------------- fold LN affine into gh_w1, emit fragment-major tf32 ------
__global__ void k_prepG(const float* __restrict__ gw1, const float* __restrict__ gb1,
                        const float* __restrict__ lng, const float* __restrict__ lnb,
                        const float* __restrict__ tscp) {
    int k = threadIdx.x;                 // 0..255 output col
    int j0 = blockIdx.x * (OUT_/8);      // 8 blocks x 129 j's
    float tsc = tscp[0];
    int nt = k >> 3, nin = k & 7;
    float s = 0.f, c = 0.f;
    for (int j=j0; j<j0+OUT_/8; j++) {
        float sc = (j >= OUT_-NT_) ? tsc : 1.0f;
        float w  = gw1[k*OUT_+j];
        float Gv = __uint_as_float(f2tf32(lng[j]*sc*w));   // tf32-rounded
        int kt = j >> 3, kin = j & 7;
        g_Gf[((size_t)(kt*32+nt)*32 + nin*4 + (kin&3))*2 + (kin>>2)] = Gv;
        s += Gv;
        c += lnb[j]*sc*w;
    }
    atomicAdd(&g_sv[k], s);
    atomicAdd(&g_cv[k], c + ((blockIdx.x==0)? gb1[k] : 0.f));
}

// ---------------- time embedding + xc, te written into F -------------------
__global__ void k_te(const float* __restrict__ x, const float* __restrict__ t,
                     const float* __restrict__ w1, const float* __restrict__ b1,
                     const float* __restrict__ w2, const float* __restrict__ b2) {
    int row = blockIdx.x*blockDim.x + threadIdx.x;
    if (row >= NROW) return;
    int b = row / L_;
    float ts = t[row] - t[b*L_];
    float r[NT_];
    #pragma unroll
    for (int j=0;j<NT_;j++) r[j] = fmaxf(ts*w1[j] + b1[j], 0.0f);
    #pragma unroll
    for (int k=0;k<NT_;k++) {
        float a = b2[k];
        #pragma unroll
        for (int j=0;j<NT_;j++) a += r[j]*w2[k*NT_+j];
        g_xc[row*IN_+2+k] = a;
        g_F[(size_t)row*OUT_ + (OUT_-NT_) + k] = a;
    }
    g_xc[row*IN_+0] = x[row*2+0];
    g_xc[row*IN_+1] = x[row*2+1];
}

// fast sigmoid pieces: z = 1/(1+e^-a), 1-z = e^-a * z
__device__ __forceinline__ void fsig(float arg, float& z, float& omz) {
    float e = __expf(-arg);
    z = __fdividef(1.0f, 1.0f + e);
    omz = e * z;
}

// ---------------- scan pass A: chunk-local a-products ----------------------
__global__ void k_scanA() {
    int c = blockIdx.x, b = blockIdx.y, dir = blockIdx.z;
    int h = threadIdx.x;
    __shared__ float xs[CH_][IN_];
    const float* xcb = g_xc + ((size_t)b*L_ + (size_t)c*CH_)*IN_;
    for (int i=h; i<CH_*IN_; i+=H_) ((float*)xs)[i] = xcb[i];
    float wz[IN_]; float bz;
    int pz = dir*2;
    #pragma unroll
    for (int i=0;i<IN_;i++) wz[i] = g_W[pz][h][i];
    bz = g_bias[pz][h];
    __syncthreads();
    float A = 1.0f;
    int s0 = (dir==0)? 0 : CH_-1;
    int ds = (dir==0)? 1 : -1;
    #pragma unroll 4
    for (int k=0;k<CH_;k++) {
        int s = s0 + k*ds;
        float arg = bz;
        #pragma unroll
        for (int i=0;i<IN_;i++) arg += xs[s][i]*wz[i];
        float z, omz; fsig(arg, z, omz);
        A *= omz;
    }
    g_P[dir][b][c][h] = A;
}

// ---------------- scan pass B1: chunk-entry cumprod states -----------------
__global__ void k_scanB1() {
    int b = blockIdx.x, dir = blockIdx.y, h = threadIdx.x;
    float run = 1.0f;
    if (dir==0) { for (int c=0;c<NC_;c++)    { g_Ae[0][b][c][h]=run; run *= g_P[0][b][c][h]; } }
    else        { for (int c=NC_-1;c>=0;c--) { g_Ae[1][b][c][h]=run; run *= g_P[1][b][c][h]; } }
}

// ---------------- scan pass C1: chunk local sums of d ----------------------
__global__ void k_scanC1() {
    int c = blockIdx.x, b = blockIdx.y, dir = blockIdx.z;
    int h = threadIdx.x;
    __shared__ float xs[CH_][IN_];
    const float* xcb = g_xc + ((size_t)b*L_ + (size_t)c*CH_)*IN_;
    for (int i=h; i<CH_*IN_; i+=H_) ((float*)xs)[i] = xcb[i];
    float wz[IN_], wh[IN_]; float bz, bh;
    int pz = dir*2, ph = dir*2+1;
    #pragma unroll
    for (int i=0;i<IN_;i++) { wz[i]=g_W[pz][h][i]; wh[i]=g_W[ph][h][i]; }
    bz = g_bias[pz][h]; bh = g_bias[ph][h];
    __syncthreads();
    float A = g_Ae[dir][b][c][h];
    float Ls = 0.0f;
    int s0  = (dir==0)? 0 : CH_-1;
    int ds  = (dir==0)? 1 : -1;
    #pragma unroll 4
    for (int k=0;k<CH_;k++) {
        int s = s0 + k*ds;
        float az = bz, ah = bh;
        #pragma unroll
        for (int i=0;i<IN_;i++) { float xv = xs[s][i]; az += xv*wz[i]; ah += xv*wh[i]; }
        float z, omz; fsig(az, z, omz);
        A *= omz;
        Ls += __fdividef(z*ah, fmaxf(A, 1e-12f));
    }
    g_Lc[dir][b][c][h] = Ls;
}

// ---------------- scan pass B2: chunk-entry cumsum states ------------------
__global__ void k_scanB2() {
    int b = blockIdx.x, dir = blockIdx.y, h = threadIdx.x;
    float run = 0.0f;
    if (dir==0) { for (int c=0;c<NC_;c++)    { g_Se[0][b][c][h]=run; run += g_Lc[0][b][c][h]; } }
    else        { for (int c=NC_-1;c>=0;c--) { g_Se[1][b][c][h]=run; run += g_Lc[1][b][c][h]; } }
}

// ---------------- scan pass C2: emit shifted h = A*S into F ----------------
__global__ void k_scanC2() {
    int c = blockIdx.x, b = blockIdx.y, dir = blockIdx.z;
    int h = threadIdx.x;
    __shared__ float xs[CH_][IN_];
    const float* xcb = g_xc + ((size_t)b*L_ + (size_t)c*CH_)*IN_;
    for (int i=h; i<CH_*IN_; i+=H_) ((float*)xs)[i] = xcb[i];
    float wz[IN_], wh[IN_]; float bz, bh;
    int pz = dir*2, ph = dir*2+1;
    #pragma unroll
    for (int i=0;i<IN_;i++) { wz[i]=g_W[pz][h][i]; wh[i]=g_W[ph][h][i]; }
    bz = g_bias[pz][h]; bh = g_bias[ph][h];
    __syncthreads();
    float A = g_Ae[dir][b][c][h];
    float S = g_Se[dir][b][c][h];
    int s0  = (dir==0)? 0 : CH_-1;
    int ds  = (dir==0)? 1 : -1;
    size_t fofs = (dir==0)? (size_t)h : (size_t)(H_ + h);
    #pragma unroll 4
    for (int k=0;k<CH_;k++) {
        int s = s0 + k*ds;
        int l = c*CH_ + s;
        g_F[((size_t)(b*L_ + l))*OUT_ + fofs] = A*S;   // state BEFORE consuming l
        float az = bz, ah = bh;
        #pragma unroll
        for (int i=0;i<IN_;i++) { float xv = xs[s][i]; az += xv*wz[i]; ah += xv*wh[i]; }
        float z, omz; fsig(az, z, omz);
        A *= omz;
        S += __fdividef(z*ah, fmaxf(A, 1e-12f));
    }
}

// ---------------- tf32 tensor-core GEMM + fused LN + gelu + w2 reduce ------
// C = F(65536x1032) @ G(1032x256), BM=64 rows/block, 512 thr = 16 warps (4m x 4n)
#define GBM 64
__global__ __launch_bounds__(512, 1) void k_gemm2(const float* __restrict__ w2,
                                                  const float* __restrict__ b2p,
                                                  float* __restrict__ out) {
    __shared__ float s_s[HH_], s_c[HH_], s_w2[HH_];
    __shared__ float s_sum[GBM], s_sq[GBM];
    __shared__ float s_mu[GBM], s_rs[GBM];
    __shared__ float s_part[GBM][4];

    int t = threadIdx.x;
    int lane = t & 31, warp = t >> 5;
    int wm = warp >> 2, wn = warp & 3;      // 4x4 warp grid
    int g  = lane >> 2, tig = lane & 3;
    int row0 = blockIdx.x * GBM;
    int r0 = row0 + wm*16 + g;              // rows r0 and r0+8

    if (t < HH_) { s_s[t] = g_sv[t]; s_c[t] = g_cv[t]; s_w2[t] = w2[t]; }

    float acc[8][4];
    #pragma unroll
    for (int i=0;i<8;i++) { acc[i][0]=0.f; acc[i][1]=0.f; acc[i][2]=0.f; acc[i][3]=0.f; }

    const float* A0 = g_F + (size_t)r0*OUT_;
    const float* A1 = g_F + (size_t)(r0+8)*OUT_;
    float ps0=0.f, pq0=0.f, ps1=0.f, pq1=0.f;

    for (int kt=0; kt<NKT; kt++) {
        int kc = kt*8 + tig;
        float a0f = __ldg(A0+kc), a1f = __ldg(A1+kc);
        float a2f = __ldg(A0+kc+4), a3f = __ldg(A1+kc+4);
        if (wn == 0) {
            ps0 += a0f + a2f;  pq0 += a0f*a0f + a2f*a2f;
            ps1 += a1f + a3f;  pq1 += a1f*a1f + a3f*a3f;
        }
        uint32_t a0 = f2tf32(a0f), a1 = f2tf32(a1f);
        uint32_t a2 = f2tf32(a2f), a3 = f2tf32(a3f);
        const float2* Bkt = (const float2*)g_Gf + ((size_t)kt*32 + wn*8)*32 + lane;
        #pragma unroll
        for (int nt=0; nt<8; nt++) {
            float2 bv = __ldg(Bkt + nt*32);
            uint32_t b0 = __float_as_uint(bv.x), b1 = __float_as_uint(bv.y);
            asm volatile(
                "mma.sync.aligned.m16n8k8.row.col.f32.tf32.tf32.f32 "
                "{%0,%1,%2,%3}, {%4,%5,%6,%7}, {%8,%9}, {%0,%1,%2,%3};"
                : "+f"(acc[nt][0]), "+f"(acc[nt][1]), "+f"(acc[nt][2]), "+f"(acc[nt][3])
                : "r"(a0), "r"(a1), "r"(a2), "r"(a3), "r"(b0), "r"(b1));
        }
    }

    // row stats: reduce over tig group (4 lanes), one warp per row-group
    if (wn == 0) {
        #pragma unroll
        for (int off=1; off<4; off<<=1) {
            ps0 += __shfl_xor_sync(0xffffffffu, ps0, off);
            pq0 += __shfl_xor_sync(0xffffffffu, pq0, off);
            ps1 += __shfl_xor_sync(0xffffffffu, ps1, off);
            pq1 += __shfl_xor_sync(0xffffffffu, pq1, off);
        }
        if (tig == 0) {
            s_sum[wm*16+g]   = ps0;  s_sq[wm*16+g]   = pq0;
            s_sum[wm*16+g+8] = ps1;  s_sq[wm*16+g+8] = pq1;
        }
    }
    __syncthreads();
    if (t < GBM) {
        float m = s_sum[t] * (1.0f/(float)OUT_);
        float v = s_sq[t]  * (1.0f/(float)OUT_) - m*m;
        s_mu[t] = m;
        s_rs[t] = rsqrtf(v + EPS_);
    }
    __syncthreads();

    float mu0 = s_mu[wm*16+g],   rs0 = s_rs[wm*16+g];
    float mu1 = s_mu[wm*16+g+8], rs1 = s_rs[wm*16+g+8];
    float po0 = 0.f, po1 = 0.f;
    #pragma unroll
    for (int nt=0; nt<8; nt++) {
        #pragma unroll
        for (int e=0; e<2; e++) {
            int col = wn*64 + nt*8 + tig*2 + e;
            float sS = s_s[col], sC = s_c[col], wv = s_w2[col];
            float v0 = (acc[nt][e]   - mu0*sS)*rs0 + sC;
            float v1 = (acc[nt][2+e] - mu1*sS)*rs1 + sC;
            float h0 = 0.5f*v0*(1.0f + erff(v0*0.70710678118654752440f));
            float h1 = 0.5f*v1*(1.0f + erff(v1*0.70710678118654752440f));
            po0 += h0*wv;
            po1 += h1*wv;
        }
    }
    #pragma unroll
    for (int off=1; off<4; off<<=1) {
        po0 += __shfl_xor_sync(0xffffffffu, po0, off);
        po1 += __shfl_xor_sync(0xffffffffu, po1, off);
    }
    if (tig == 0) {
        s_part[wm*16+g][wn]   = po0;
        s_part[wm*16+g+8][wn] = po1;
    }
    __syncthreads();
    if (t < GBM) {
        out[row0 + t] = b2p[0] + s_part[t][0] + s_part[t][1] + s_part[t][2] + s_part[t][3];
    }
}

// ---------------- launch ---------------------------------------------------
extern "C" void kernel_launch(void* const* d_in, const int* in_sizes, int n_in,
                              void* d_out, int out_size) {
    const float* x      = (const float*)d_in[0];
    const float* t      = (const float*)d_in[1];
    const float* te_w1  = (const float*)d_in[2];
    const float* te_b1  = (const float*)d_in[3];
    const float* te_w2  = (const float*)d_in[4];
    const float* te_b2  = (const float*)d_in[5];
    const float* fproj_w= (const float*)d_in[6];
    const float* fproj_b= (const float*)d_in[7];
    const float* bproj_w= (const float*)d_in[8];
    const float* bproj_b= (const float*)d_in[9];
    const float* fz_w   = (const float*)d_in[10];
    const float* fz_b   = (const float*)d_in[11];
    const float* fh_w   = (const float*)d_in[12];
    const float* fh_b   = (const float*)d_in[13];
    const float* bz_w   = (const float*)d_in[14];
    const float* bz_b   = (const float*)d_in[15];
    const float* bh_w   = (const float*)d_in[16];
    const float* bh_b   = (const float*)d_in[17];
    const float* ln_g   = (const float*)d_in[18];
    const float* ln_b   = (const float*)d_in[19];
    const float* tsc    = (const float*)d_in[20];
    const float* gh_w1  = (const float*)d_in[21];
    const float* gh_b1  = (const float*)d_in[22];
    const float* gh_w2  = (const float*)d_in[23];
    const float* gh_b2  = (const float*)d_in[24];
    float* out = (float*)d_out;

    k_zero<<<(4*H_*IN_ + 255)/256, 256>>>();
    k_fold<<<dim3(4, 8), H_>>>(fz_w, fh_w, bz_w, bh_w, fz_b, fh_b, bz_b, bh_b,
                               fproj_w, fproj_b, bproj_w, bproj_b);
    k_prepG<<<8, HH_>>>(gh_w1, gh_b1, ln_g, ln_b, tsc);
    k_te<<<NROW/256, 256>>>(x, t, te_w1, te_b1, te_w2, te_b2);
    k_scanA <<<dim3(NC_, B_, 2), H_>>>();
    k_scanB1<<<dim3(B_, 2), H_>>>();
    k_scanC1<<<dim3(NC_, B_, 2), H_>>>();
    k_scanB2<<<dim3(B_, 2), H_>>>();
    k_scanC2<<<dim3(NC_, B_, 2), H_>>>();
    k_gemm2<<<NROW/GBM, 512>>>(gh_w2, gh_b2, out);
}

// round 4
// speedup vs baseline: 2.6710x; 1.4585x over previous
#include <cuda_runtime.h>
#include <cuda_fp16.h>
#include <math.h>
#include <stdint.h>

#define B_  16
#define L_  4096
#define H_  512
#define NT_ 8
#define IN_ 10
#define OUT_ 1032
#define KP   1056            // padded K (66 chunks of 16)
#define NCH16 66
#define HH_ 256
#define NC_ 16
#define CH_ 256
#define EPS_ 1e-5f
#define NROW (B_*L_)

// ---------------- device scratch (static, allocation-free) ----------------
__device__ float g_xc[NROW*IN_];
__device__ float g_F [(size_t)NROW*KP];             // features, padded stride (pads stay 0)
__device__ float g_W [4][H_][IN_];
__device__ float g_bias[4][H_];
__device__ float g_P [2][B_][NC_][H_];
__device__ float g_Ae[2][B_][NC_][H_];
__device__ float g_Lc[2][B_][NC_][H_];
__device__ float g_Se[2][B_][NC_][H_];
__device__ __half g_Gh[(size_t)NCH16*32*128];       // B fp16 fragment-major (pads 0)
__device__ float g_sv[HH_];
__device__ float g_cv[HH_];

// ---------------- zero accumulators ----------------------------------------
__global__ void k_zero() {
    int i = blockIdx.x*blockDim.x + threadIdx.x;
    if (i < 4*H_*IN_) ((float*)g_W)[i] = 0.f;
    if (i < 4*H_)     ((float*)g_bias)[i] = 0.f;
    if (i < HH_)      { g_sv[i] = 0.f; g_cv[i] = 0.f; }
}

// ---------------- fold gate weights through the 10-dim projection ----------
__global__ void k_fold(const float* __restrict__ fz, const float* __restrict__ fh,
                       const float* __restrict__ bz, const float* __restrict__ bh,
                       const float* __restrict__ fzb, const float* __restrict__ fhb,
                       const float* __restrict__ bzb, const float* __restrict__ bhb,
                       const float* __restrict__ fp, const float* __restrict__ fpb,
                       const float* __restrict__ bp, const float* __restrict__ bpb) {
    int p = blockIdx.x, sl = blockIdx.y;
    int h = threadIdx.x;
    const float* zw = (p==0)?fz:(p==1)?fh:(p==2)?bz:bh;
    const float* zb = (p==0)?fzb:(p==1)?fhb:(p==2)?bzb:bhb;
    const float* pw = (p<2)?fp:bp;
    const float* pb = (p<2)?fpb:bpb;
    float acc[IN_]; float ab = 0.f;
    #pragma unroll
    for (int i=0;i<IN_;i++) acc[i]=0.f;
    for (int d=sl*64; d<sl*64+64; d++) {
        float w = zw[h*H_+d];
        #pragma unroll
        for (int i=0;i<IN_;i++) acc[i] += w*pw[d*IN_+i];
        ab += w*pb[d];
    }
    #pragma unroll
    for (int i=0;i<IN_;i++) atomicAdd(&g_W[p][h][i], acc[i]);
    atomicAdd(&g_bias[p][h], ab + ((sl==0)? zb[h] : 0.f));
}

// ---------------- fold LN affine into gh_w1, emit fp16 fragment-major B ----
// m16n8k16 B fragment (col-major k16 x n8): lane = n%8*4 + (k%8)/2,
// reg = k/8, half = k%1 ... (see PTX ISA layout)
__global__ void k_prepG(const float* __restrict__ gw1, const float* __restrict__ gb1,
                        const float* __restrict__ lng, const float* __restrict__ lnb,
                        const float* __restrict__ tscp) {
    int k = threadIdx.x;                 // output col n, 0..255
    int j0 = blockIdx.x * (OUT_/8);
    float tsc = tscp[0];
    int nt = k >> 3, ng = k & 7;
    float s = 0.f, c = 0.f;
    for (int j=j0; j<j0+OUT_/8; j++) {
        float sc = (j >= OUT_-NT_) ? tsc : 1.0f;
        float w  = gw1[k*OUT_+j];
        __half Gh = __float2half_rn(lng[j]*sc*w);
        int kt = j >> 4, kin = j & 15;
        int lane = ng*4 + ((kin & 7) >> 1);
        int reg = kin >> 3, hs = kin & 1;
        g_Gh[(((size_t)(kt*32 + nt)*32 + lane)*2 + reg)*2 + hs] = Gh;
        s += __half2float(Gh);
        c += lnb[j]*sc*w;
    }
    atomicAdd(&g_sv[k], s);
    atomicAdd(&g_cv[k], c + ((blockIdx.x==0)? gb1[k] : 0.f));
}

// ---------------- time embedding + xc, te into F ---------------------------
__global__ void k_te(const float* __restrict__ x, const float* __restrict__ t,
                     const float* __restrict__ w1, const float* __restrict__ b1,
                     const float* __restrict__ w2, const float* __restrict__ b2) {
    int row = blockIdx.x*blockDim.x + threadIdx.x;
    if (row >= NROW) return;
    int b = row / L_;
    float ts = t[row] - t[b*L_];
    float r[NT_];
    #pragma unroll
    for (int j=0;j<NT_;j++) r[j] = fmaxf(ts*w1[j] + b1[j], 0.0f);
    #pragma unroll
    for (int k=0;k<NT_;k++) {
        float a = b2[k];
        #pragma unroll
        for (int j=0;j<NT_;j++) a += r[j]*w2[k*NT_+j];
        g_xc[row*IN_+2+k] = a;
        g_F[(size_t)row*KP + (OUT_-NT_) + k] = a;
    }
    g_xc[row*IN_+0] = x[row*2+0];
    g_xc[row*IN_+1] = x[row*2+1];
}

// fast sigmoid pieces
__device__ __forceinline__ void fsig(float arg, float& z, float& omz) {
    float e = __expf(-arg);
    z = __fdividef(1.0f, 1.0f + e);
    omz = e * z;
}

// ---------------- scan passes ----------------------------------------------
__global__ void k_scanA() {
    int c = blockIdx.x, b = blockIdx.y, dir = blockIdx.z;
    int h = threadIdx.x;
    __shared__ float xs[CH_][IN_];
    const float* xcb = g_xc + ((size_t)b*L_ + (size_t)c*CH_)*IN_;
    for (int i=h; i<CH_*IN_; i+=H_) ((float*)xs)[i] = xcb[i];
    float wz[IN_]; float bz;
    int pz = dir*2;
    #pragma unroll
    for (int i=0;i<IN_;i++) wz[i] = g_W[pz][h][i];
    bz = g_bias[pz][h];
    __syncthreads();
    float A = 1.0f;
    int s0 = (dir==0)? 0 : CH_-1;
    int ds = (dir==0)? 1 : -1;
    #pragma unroll 4
    for (int k=0;k<CH_;k++) {
        int s = s0 + k*ds;
        float arg = bz;
        #pragma unroll
        for (int i=0;i<IN_;i++) arg += xs[s][i]*wz[i];
        float z, omz; fsig(arg, z, omz);
        A *= omz;
    }
    g_P[dir][b][c][h] = A;
}

__global__ void k_scanB1() {
    int b = blockIdx.x, dir = blockIdx.y, h = threadIdx.x;
    float run = 1.0f;
    if (dir==0) { for (int c=0;c<NC_;c++)    { g_Ae[0][b][c][h]=run; run *= g_P[0][b][c][h]; } }
    else        { for (int c=NC_-1;c>=0;c--) { g_Ae[1][b][c][h]=run; run *= g_P[1][b][c][h]; } }
}

__global__ void k_scanC1() {
    int c = blockIdx.x, b = blockIdx.y, dir = blockIdx.z;
    int h = threadIdx.x;
    __shared__ float xs[CH_][IN_];
    const float* xcb = g_xc + ((size_t)b*L_ + (size_t)c*CH_)*IN_;
    for (int i=h; i<CH_*IN_; i+=H_) ((float*)xs)[i] = xcb[i];
    float wz[IN_], wh[IN_]; float bz, bh;
    int pz = dir*2, ph = dir*2+1;
    #pragma unroll
    for (int i=0;i<IN_;i++) { wz[i]=g_W[pz][h][i]; wh[i]=g_W[ph][h][i]; }
    bz = g_bias[pz][h]; bh = g_bias[ph][h];
    __syncthreads();
    float A = g_Ae[dir][b][c][h];
    float Ls = 0.0f;
    int s0  = (dir==0)? 0 : CH_-1;
    int ds  = (dir==0)? 1 : -1;
    #pragma unroll 4
    for (int k=0;k<CH_;k++) {
        int s = s0 + k*ds;
        float az = bz, ah = bh;
        #pragma unroll
        for (int i=0;i<IN_;i++) { float xv = xs[s][i]; az += xv*wz[i]; ah += xv*wh[i]; }
        float z, omz; fsig(az, z, omz);
        A *= omz;
        Ls += __fdividef(z*ah, fmaxf(A, 1e-12f));
    }
    g_Lc[dir][b][c][h] = Ls;
}

__global__ void k_scanB2() {
    int b = blockIdx.x, dir = blockIdx.y, h = threadIdx.x;
    float run = 0.0f;
    if (dir==0) { for (int c=0;c<NC_;c++)    { g_Se[0][b][c][h]=run; run += g_Lc[0][b][c][h]; } }
    else        { for (int c=NC_-1;c>=0;c--) { g_Se[1][b][c][h]=run; run += g_Lc[1][b][c][h]; } }
}

__global__ void k_scanC2() {
    int c = blockIdx.x, b = blockIdx.y, dir = blockIdx.z;
    int h = threadIdx.x;
    __shared__ float xs[CH_][IN_];
    const float* xcb = g_xc + ((size_t)b*L_ + (size_t)c*CH_)*IN_;
    for (int i=h; i<CH_*IN_; i+=H_) ((float*)xs)[i] = xcb[i];
    float wz[IN_], wh[IN_]; float bz, bh;
    int pz = dir*2, ph = dir*2+1;
    #pragma unroll
    for (int i=0;i<IN_;i++) { wz[i]=g_W[pz][h][i]; wh[i]=g_W[ph][h][i]; }
    bz = g_bias[pz][h]; bh = g_bias[ph][h];
    __syncthreads();
    float A = g_Ae[dir][b][c][h];
    float S = g_Se[dir][b][c][h];
    int s0  = (dir==0)? 0 : CH_-1;
    int ds  = (dir==0)? 1 : -1;
    size_t fofs = (dir==0)? (size_t)h : (size_t)(H_ + h);
    #pragma unroll 4
    for (int k=0;k<CH_;k++) {
        int s = s0 + k*ds;
        int l = c*CH_ + s;
        g_F[((size_t)(b*L_ + l))*KP + fofs] = A*S;
        float az = bz, ah = bh;
        #pragma unroll
        for (int i=0;i<IN_;i++) { float xv = xs[s][i]; az += xv*wz[i]; ah += xv*wh[i]; }
        float z, omz; fsig(az, z, omz);
        A *= omz;
        S += __fdividef(z*ah, fmaxf(A, 1e-12f));
    }
}

// ---------------- fp16 mma GEMM + fused LN + gelu + w2 reduce --------------
// C = F(65536x1056) @ G(1056x256). 64 rows/block, 512 thr = 16 warps (4m x 4n).
#define GBM 64
__global__ __launch_bounds__(512, 1) void k_gemm3(const float* __restrict__ w2,
                                                  const float* __restrict__ b2p,
                                                  float* __restrict__ out) {
    __shared__ float s_s[HH_], s_c[HH_], s_w2[HH_];
    __shared__ float s_sum[GBM], s_sq[GBM];
    __shared__ float s_mu[GBM], s_rs[GBM];
    __shared__ float s_part[GBM][4];

    int t = threadIdx.x;
    int lane = t & 31, warp = t >> 5;
    int wm = warp >> 2, wn = warp & 3;      // 4m x 4n warp grid
    int g  = lane >> 2, tig = lane & 3;
    int row0 = blockIdx.x * GBM;
    int r0 = row0 + wm*16 + g;

    if (t < HH_) { s_s[t] = g_sv[t]; s_c[t] = g_cv[t]; s_w2[t] = w2[t]; }

    float acc[8][4];
    #pragma unroll
    for (int i=0;i<8;i++) { acc[i][0]=0.f; acc[i][1]=0.f; acc[i][2]=0.f; acc[i][3]=0.f; }

    const float* Ar0 = g_F + (size_t)r0*KP     + tig*2;
    const float* Ar8 = Ar0 + 8*KP;
    const uint2* Bp  = ((const uint2*)g_Gh) + ((size_t)wn*8)*32 + lane;

    float2 fA0 = __ldg((const float2*)(Ar0));
    float2 fA1 = __ldg((const float2*)(Ar8));
    float2 fA2 = __ldg((const float2*)(Ar0 + 8));
    float2 fA3 = __ldg((const float2*)(Ar8 + 8));
    uint2 fB[8];
    #pragma unroll
    for (int nt=0; nt<8; nt++) fB[nt] = __ldg(Bp + nt*32);

    float ps0=0.f, pq0=0.f, ps1=0.f, pq1=0.f;

    for (int ch=0; ch<NCH16; ch++) {
        if (wn == 0) {
            ps0 += fA0.x+fA0.y+fA2.x+fA2.y;
            pq0 += fA0.x*fA0.x + fA0.y*fA0.y + fA2.x*fA2.x + fA2.y*fA2.y;
            ps1 += fA1.x+fA1.y+fA3.x+fA3.y;
            pq1 += fA1.x*fA1.x + fA1.y*fA1.y + fA3.x*fA3.x + fA3.y*fA3.y;
        }
        __half2 h0 = __floats2half2_rn(fA0.x, fA0.y);
        __half2 h1 = __floats2half2_rn(fA1.x, fA1.y);
        __half2 h2 = __floats2half2_rn(fA2.x, fA2.y);
        __half2 h3 = __floats2half2_rn(fA3.x, fA3.y);
        uint32_t a0 = *reinterpret_cast<uint32_t*>(&h0);
        uint32_t a1 = *reinterpret_cast<uint32_t*>(&h1);
        uint32_t a2 = *reinterpret_cast<uint32_t*>(&h2);
        uint32_t a3 = *reinterpret_cast<uint32_t*>(&h3);
        #pragma unroll
        for (int nt=0; nt<8; nt++) {
            asm volatile(
                "mma.sync.aligned.m16n8k16.row.col.f32.f16.f16.f32 "
                "{%0,%1,%2,%3}, {%4,%5,%6,%7}, {%8,%9}, {%0,%1,%2,%3};"
                : "+f"(acc[nt][0]), "+f"(acc[nt][1]), "+f"(acc[nt][2]), "+f"(acc[nt][3])
                : "r"(a0), "r"(a1), "r"(a2), "r"(a3), "r"(fB[nt].x), "r"(fB[nt].y));
        }
        if (ch+1 < NCH16) {
            int k0 = (ch+1)*16;
            fA0 = __ldg((const float2*)(Ar0 + k0));
            fA1 = __ldg((const float2*)(Ar8 + k0));
            fA2 = __ldg((const float2*)(Ar0 + k0 + 8));
            fA3 = __ldg((const float2*)(Ar8 + k0 + 8));
            const uint2* Bn = Bp + (size_t)(ch+1)*1024;
            #pragma unroll
            for (int nt=0; nt<8; nt++) fB[nt] = __ldg(Bn + nt*32);
        }
    }

    // row stats: reduce over tig group (4 lanes)
    if (wn == 0) {
        #pragma unroll
        for (int off=1; off<4; off<<=1) {
            ps0 += __shfl_xor_sync(0xffffffffu, ps0, off);
            pq0 += __shfl_xor_sync(0xffffffffu, pq0, off);
            ps1 += __shfl_xor_sync(0xffffffffu, ps1, off);
            pq1 += __shfl_xor_sync(0xffffffffu, pq1, off);
        }
        if (tig == 0) {
            s_sum[wm*16+g]   = ps0;  s_sq[wm*16+g]   = pq0;
            s_sum[wm*16+g+8] = ps1;  s_sq[wm*16+g+8] = pq1;
        }
    }
    __syncthreads();
    if (t < GBM) {
        float m = s_sum[t] * (1.0f/(float)OUT_);
        float v = s_sq[t]  * (1.0f/(float)OUT_) - m*m;
        s_mu[t] = m;
        s_rs[t] = rsqrtf(v + EPS_);
    }
    __syncthreads();

    float mu0 = s_mu[wm*16+g],   rs0 = s_rs[wm*16+g];
    float mu1 = s_mu[wm*16+g+8], rs1 = s_rs[wm*16+g+8];
    float po0 = 0.f, po1 = 0.f;
    #pragma unroll
    for (int nt=0; nt<8; nt++) {
        #pragma unroll
        for (int e=0; e<2; e++) {
            int col = wn*64 + nt*8 + tig*2 + e;
            float sS = s_s[col], sC = s_c[col], wv = s_w2[col];
            float v0 = (acc[nt][e]   - mu0*sS)*rs0 + sC;
            float v1 = (acc[nt][2+e] - mu1*sS)*rs1 + sC;
            float h0 = 0.5f*v0*(1.0f + erff(v0*0.70710678118654752440f));
            float h1 = 0.5f*v1*(1.0f + erff(v1*0.70710678118654752440f));
            po0 += h0*wv;
            po1 += h1*wv;
        }
    }
    #pragma unroll
    for (int off=1; off<4; off<<=1) {
        po0 += __shfl_xor_sync(0xffffffffu, po0, off);
        po1 += __shfl_xor_sync(0xffffffffu, po1, off);
    }
    if (tig == 0) {
        s_part[wm*16+g][wn]   = po0;
        s_part[wm*16+g+8][wn] = po1;
    }
    __syncthreads();
    if (t < GBM) {
        out[row0 + t] = b2p[0] + s_part[t][0] + s_part[t][1] + s_part[t][2] + s_part[t][3];
    }
}

// ---------------- launch ---------------------------------------------------
extern "C" void kernel_launch(void* const* d_in, const int* in_sizes, int n_in,
                              void* d_out, int out_size) {
    const float* x      = (const float*)d_in[0];
    const float* t      = (const float*)d_in[1];
    const float* te_w1  = (const float*)d_in[2];
    const float* te_b1  = (const float*)d_in[3];
    const float* te_w2  = (const float*)d_in[4];
    const float* te_b2  = (const float*)d_in[5];
    const float* fproj_w= (const float*)d_in[6];
    const float* fproj_b= (const float*)d_in[7];
    const float* bproj_w= (const float*)d_in[8];
    const float* bproj_b= (const float*)d_in[9];
    const float* fz_w   = (const float*)d_in[10];
    const float* fz_b   = (const float*)d_in[11];
    const float* fh_w   = (const float*)d_in[12];
    const float* fh_b   = (const float*)d_in[13];
    const float* bz_w   = (const float*)d_in[14];
    const float* bz_b   = (const float*)d_in[15];
    const float* bh_w   = (const float*)d_in[16];
    const float* bh_b   = (const float*)d_in[17];
    const float* ln_g   = (const float*)d_in[18];
    const float* ln_b   = (const float*)d_in[19];
    const float* tsc    = (const float*)d_in[20];
    const float* gh_w1  = (const float*)d_in[21];
    const float* gh_b1  = (const float*)d_in[22];
    const float* gh_w2  = (const float*)d_in[23];
    const float* gh_b2  = (const float*)d_in[24];
    float* out = (float*)d_out;

    k_zero<<<(4*H_*IN_ + 255)/256, 256>>>();
    k_fold<<<dim3(4, 8), H_>>>(fz_w, fh_w, bz_w, bh_w, fz_b, fh_b, bz_b, bh_b,
                               fproj_w, fproj_b, bproj_w, bproj_b);
    k_prepG<<<8, HH_>>>(gh_w1, gh_b1, ln_g, ln_b, tsc);
    k_te<<<NROW/256, 256>>>(x, t, te_w1, te_b1, te_w2, te_b2);
    k_scanA <<<dim3(NC_, B_, 2), H_>>>();
    k_scanB1<<<dim3(B_, 2), H_>>>();
    k_scanC1<<<dim3(NC_, B_, 2), H_>>>();
    k_scanB2<<<dim3(B_, 2), H_>>>();
    k_scanC2<<<dim3(NC_, B_, 2), H_>>>();
    k_gemm3<<<NROW/GBM, 512>>>(gh_w2, gh_b2, out);
}